// round 5
// baseline (speedup 1.0000x reference)
#include <cuda_runtime.h>
#include <cstdint>

// ---------------------------------------------------------------------------
// Fused causal attention head via warp-level tf32 mma.sync. One CTA per batch,
// 2 CTAs/SM. Q and P in registers; K/V/W in SMEM with paired-k layouts so all
// B-fragments load as single conflict-free LDS.64. X staged through SMEM
// (transiently in the K region) to fix the scalar-LDG wavefront blowup.
//   x:[4096,128,64] f32, Wq/Wk/Wv:[64,64] f32, out:[4096,128,64] f32
// ---------------------------------------------------------------------------

#define DEVINL __device__ __forceinline__

static constexpr int T = 128;
static constexpr int C = 64;
static constexpr int H = 64;

// Paired-k layout: within each 8-wide k-group, element j sits at position
// pos(j) = 2*(j&3) + (j>>2), so the mma B-frag pair (j=q4, j=q4+4) is adjacent
// and loads as one LDS.64.
//  W/K/X: row-indexed, stride 72 words (72%32==8 -> conflict-free LDS.64)
//  V: token-interleaved rows, stride 136 words (136%32==8 -> conflict-free)
static constexpr int WST = 72;    // W and X and K stride (words)
static constexpr int VST = 136;   // V stride (words)

static constexpr uint32_t WSZ  = 64 * WST * 4;            // 18432 per W matrix
static constexpr uint32_t SM_W = 0;                       // Wk@0, Wv@18432; Wq later @0
static constexpr uint32_t SM_K = 2 * WSZ;                 // 36864 (X staged here first)
static constexpr uint32_t SM_X = SM_K;
static constexpr uint32_t SM_V = SM_K + 128 * WST * 4;    // 73728
static constexpr uint32_t SM_TOT = SM_V + 64 * VST * 4;   // 108544 -> 2 CTAs/SM

DEVINL uint32_t f2tf(float f) {
    uint32_t r; asm("cvt.rna.tf32.f32 %0, %1;" : "=r"(r) : "f"(f)); return r;
}
DEVINL float ex2f(float x) {
    float y; asm("ex2.approx.ftz.f32 %0, %1;" : "=f"(y) : "f"(x)); return y;
}
DEVINL void sts32(uint32_t a, uint32_t v) {
    asm volatile("st.shared.b32 [%0], %1;" :: "r"(a), "r"(v) : "memory");
}
DEVINL uint2 lds64(uint32_t a) {
    uint2 v;
    asm volatile("ld.shared.v2.b32 {%0,%1}, [%2];" : "=r"(v.x), "=r"(v.y) : "r"(a));
    return v;
}

// D += A(16x8) * B(8x8), tf32, fp32 accum
DEVINL void mma8(float d[4], const uint32_t a[4], uint32_t b0, uint32_t b1) {
    asm volatile(
        "mma.sync.aligned.m16n8k8.row.col.f32.tf32.tf32.f32 "
        "{%0,%1,%2,%3}, {%4,%5,%6,%7}, {%8,%9}, {%0,%1,%2,%3};"
        : "+f"(d[0]), "+f"(d[1]), "+f"(d[2]), "+f"(d[3])
        : "r"(a[0]), "r"(a[1]), "r"(a[2]), "r"(a[3]), "r"(b0), "r"(b1));
}

extern "C" __global__ void __launch_bounds__(256, 2)
attn_head_kernel(const float* __restrict__ xg, const float* __restrict__ wqg,
                 const float* __restrict__ wkg, const float* __restrict__ wvg,
                 float* __restrict__ outg)
{
    extern __shared__ __align__(16) char smc[];
    const uint32_t sm = [&] { uint32_t a;
        asm("{ .reg .u64 t; cvta.to.shared.u64 t, %1; cvt.u32.u64 %0, t; }"
            : "=r"(a) : "l"(smc)); return a; }();
    const int tid  = threadIdx.x;
    const int lane = tid & 31;
    const int w    = tid >> 5;          // warp 0..7
    const int b    = blockIdx.x;
    const int g    = lane >> 2;         // group id 0..7
    const int q4   = lane & 3;          // thread-in-group 0..3
    const int r_lo = 16 * w + g;        // CTA-local rows owned by this lane
    const int r_hi = r_lo + 8;
    const bool odd = (q4 & 1);
    const int half = q4 >> 1;
    // K-store position for output col 2*q4 within its 8-group
    const int pos_a = ((q4 & 1) << 2) | (q4 >> 1);

    // ---- Prefetch Wq into registers (staged to SMEM after phase 1a) ----
    float4 wqv[4];
    #pragma unroll
    for (int j = 0; j < 4; j++)
        wqv[j] = reinterpret_cast<const float4*>(wqg)[tid + j * 256];

    // ---- Stage X (coalesced LDG.128 -> paired-layout STS, tf32) into SM_X ----
    {
        const float4* xp = reinterpret_cast<const float4*>(xg + (size_t)b * T * C);
        #pragma unroll
        for (int j = 0; j < 8; j++) {
            int i = tid + j * 256;          // 0..2047 float4
            int row = i >> 4, c4 = i & 15;  // 16 float4 per 64-col row
            float4 v = xp[i];
            uint32_t base = sm + SM_X + (row * WST + (c4 >> 1) * 8 + (c4 & 1)) * 4;
            sts32(base + 0 * 8, f2tf(v.x)); sts32(base + 1 * 8, f2tf(v.y));
            sts32(base + 2 * 8, f2tf(v.z)); sts32(base + 3 * 8, f2tf(v.w));
        }
    }
    // ---- Stage Wk, Wv (paired layout, tf32) ----
    #pragma unroll
    for (int m = 0; m < 2; m++) {
        const float* wsrc = (m == 0) ? wkg : wvg;
        #pragma unroll
        for (int j = 0; j < 4; j++) {
            int i = tid + j * 256;          // 0..1023 float4
            int h = i >> 4, c4 = i & 15;
            float4 v = reinterpret_cast<const float4*>(wsrc)[i];
            uint32_t base = sm + SM_W + m * WSZ + (h * WST + (c4 >> 1) * 8 + (c4 & 1)) * 4;
            sts32(base + 0 * 8, f2tf(v.x)); sts32(base + 1 * 8, f2tf(v.y));
            sts32(base + 2 * 8, f2tf(v.z)); sts32(base + 3 * 8, f2tf(v.w));
        }
    }
    __syncthreads();

    // ---- A-fragments of X from SMEM (LDS.64, conflict-free) ----
    uint32_t ax[8][4];
    #pragma unroll
    for (int kt = 0; kt < 8; kt++) {
        uint2 lo = lds64(sm + SM_X + (r_lo * WST + kt * 8 + 2 * q4) * 4);
        uint2 hi = lds64(sm + SM_X + (r_hi * WST + kt * 8 + 2 * q4) * 4);
        ax[kt][0] = lo.x; ax[kt][2] = lo.y;
        ax[kt][1] = hi.x; ax[kt][3] = hi.y;
    }
    __syncthreads();   // everyone done reading X before K overwrites the region

    // ---- Phase 1a: K = X*Wk^T, V = X*Wv^T (K region overwrites X) ----
    // V row-interleave params for this lane's output rows
    const int vr_lo = 8 * w + (g & 3);
    const int vp    = g >> 2;
    #pragma unroll
    for (int m = 0; m < 2; m++) {
        const uint32_t wbase = sm + SM_W + m * WSZ;
        #pragma unroll
        for (int nt = 0; nt < 8; nt++) {
            float acc[4] = {0.f, 0.f, 0.f, 0.f};
            #pragma unroll
            for (int kt = 0; kt < 8; kt++) {
                uint2 bb = lds64(wbase + ((nt * 8 + g) * WST + kt * 8 + 2 * q4) * 4);
                mma8(acc, ax[kt], bb.x, bb.y);
            }
            if (m == 0) {   // K: row = token, paired along feature
                uint32_t a0 = sm + SM_K + (r_lo * WST + nt * 8 + pos_a) * 4;
                sts32(a0, f2tf(acc[0])); sts32(a0 + 8, f2tf(acc[1]));
                uint32_t a1 = sm + SM_K + (r_hi * WST + nt * 8 + pos_a) * 4;
                sts32(a1, f2tf(acc[2])); sts32(a1 + 8, f2tf(acc[3]));
            } else {        // V: token-interleaved rows, feature doubled
                uint32_t a0 = sm + SM_V + (vr_lo * VST + (nt * 8 + 2 * q4) * 2 + vp) * 4;
                sts32(a0, f2tf(acc[0])); sts32(a0 + 8, f2tf(acc[1]));
                uint32_t a1 = sm + SM_V + ((vr_lo + 4) * VST + (nt * 8 + 2 * q4) * 2 + vp) * 4;
                sts32(a1, f2tf(acc[2])); sts32(a1 + 8, f2tf(acc[3]));
            }
        }
    }
    __syncthreads();   // K/V complete; Wk region free

    // ---- Phase 1b: stage Wq (pre-scaled by 1/sqrt(64)) over Wk region ----
    #pragma unroll
    for (int j = 0; j < 4; j++) {
        int i = tid + j * 256;
        int h = i >> 4, c4 = i & 15;
        float4 v = wqv[j];
        uint32_t base = sm + SM_W + (h * WST + (c4 >> 1) * 8 + (c4 & 1)) * 4;
        sts32(base + 0 * 8, f2tf(v.x * 0.125f)); sts32(base + 1 * 8, f2tf(v.y * 0.125f));
        sts32(base + 2 * 8, f2tf(v.z * 0.125f)); sts32(base + 3 * 8, f2tf(v.w * 0.125f));
    }
    __syncthreads();

    // ---- Phase 1c: Q = X*Wq^T -> registers (accumulator layout) ----
    float q[8][4];
    #pragma unroll
    for (int nt = 0; nt < 8; nt++) {
        q[nt][0] = q[nt][1] = q[nt][2] = q[nt][3] = 0.f;
        #pragma unroll
        for (int kt = 0; kt < 8; kt++) {
            uint2 bb = lds64(sm + SM_W + ((nt * 8 + g) * WST + kt * 8 + 2 * q4) * 4);
            mma8(q[nt], ax[kt], bb.x, bb.y);
        }
    }

    // ---- Accum layout -> A-fragment layout via quad shuffles ----
    uint32_t aq[8][4];
    #pragma unroll
    for (int kt = 0; kt < 8; kt++) {
        float t0 = __shfl_sync(~0u, q[kt][0], half, 4);
        float t1 = __shfl_sync(~0u, q[kt][1], half, 4);
        float t2 = __shfl_sync(~0u, q[kt][2], half, 4);
        float t3 = __shfl_sync(~0u, q[kt][3], half, 4);
        float u0 = __shfl_sync(~0u, q[kt][0], half + 2, 4);
        float u1 = __shfl_sync(~0u, q[kt][1], half + 2, 4);
        float u2 = __shfl_sync(~0u, q[kt][2], half + 2, 4);
        float u3 = __shfl_sync(~0u, q[kt][3], half + 2, 4);
        aq[kt][0] = f2tf(odd ? t1 : t0);
        aq[kt][1] = f2tf(odd ? t3 : t2);
        aq[kt][2] = f2tf(odd ? u1 : u0);
        aq[kt][3] = f2tf(odd ? u3 : u2);
    }

    // ---- Phase 2: S = Q * K^T (causal: skip fully-masked n-tiles) ----
    float s[16][4];
    #pragma unroll
    for (int nt = 0; nt < 16; nt++)
        s[nt][0] = s[nt][1] = s[nt][2] = s[nt][3] = 0.f;
    const int tile_max = 2 * w + 2;
    #pragma unroll
    for (int nt = 0; nt < 16; nt++) {
        if (nt < tile_max) {
            #pragma unroll
            for (int kt = 0; kt < 8; kt++) {
                uint2 bb = lds64(sm + SM_K + ((nt * 8 + g) * WST + kt * 8 + 2 * q4) * 4);
                mma8(s[nt], aq[kt], bb.x, bb.y);
            }
        }
    }

    // ---- Causal softmax in registers (row spread over a lane quad) ----
    float m_lo = -1e30f, m_hi = -1e30f;
    #pragma unroll
    for (int nt = 0; nt < 16; nt++) {
        #pragma unroll
        for (int e = 0; e < 2; e++) {
            int col = nt * 8 + 2 * q4 + e;
            if (col <= r_lo) m_lo = fmaxf(m_lo, s[nt][e]);
            if (col <= r_hi) m_hi = fmaxf(m_hi, s[nt][2 + e]);
        }
    }
    m_lo = fmaxf(m_lo, __shfl_xor_sync(~0u, m_lo, 1));
    m_lo = fmaxf(m_lo, __shfl_xor_sync(~0u, m_lo, 2));
    m_hi = fmaxf(m_hi, __shfl_xor_sync(~0u, m_hi, 1));
    m_hi = fmaxf(m_hi, __shfl_xor_sync(~0u, m_hi, 2));

    const float L2E = 1.4426950408889634f;
    float sum_lo = 0.f, sum_hi = 0.f;
    #pragma unroll
    for (int nt = 0; nt < 16; nt++) {
        #pragma unroll
        for (int e = 0; e < 2; e++) {
            int col = nt * 8 + 2 * q4 + e;
            float pl = (col <= r_lo) ? ex2f((s[nt][e]     - m_lo) * L2E) : 0.f;
            float ph = (col <= r_hi) ? ex2f((s[nt][2 + e] - m_hi) * L2E) : 0.f;
            sum_lo += pl; sum_hi += ph;
            s[nt][e]     = __uint_as_float(f2tf(pl));   // P, tf32 bits, accum layout
            s[nt][2 + e] = __uint_as_float(f2tf(ph));
        }
    }
    sum_lo += __shfl_xor_sync(~0u, sum_lo, 1);
    sum_lo += __shfl_xor_sync(~0u, sum_lo, 2);
    sum_hi += __shfl_xor_sync(~0u, sum_hi, 1);
    sum_hi += __shfl_xor_sync(~0u, sum_hi, 2);
    const float inv_lo = 1.f / sum_lo, inv_hi = 1.f / sum_hi;

    // ---- Phase 4: O = P * V (P -> A-frags on the fly; V via paired LDS.64) ----
    float o[8][4];
    #pragma unroll
    for (int nt = 0; nt < 8; nt++)
        o[nt][0] = o[nt][1] = o[nt][2] = o[nt][3] = 0.f;
    #pragma unroll
    for (int kt = 0; kt < 16; kt++) {
        if (kt < tile_max) {
            float t0 = __shfl_sync(~0u, s[kt][0], half, 4);
            float t1 = __shfl_sync(~0u, s[kt][1], half, 4);
            float t2 = __shfl_sync(~0u, s[kt][2], half, 4);
            float t3 = __shfl_sync(~0u, s[kt][3], half, 4);
            float u0 = __shfl_sync(~0u, s[kt][0], half + 2, 4);
            float u1 = __shfl_sync(~0u, s[kt][1], half + 2, 4);
            float u2 = __shfl_sync(~0u, s[kt][2], half + 2, 4);
            float u3 = __shfl_sync(~0u, s[kt][3], half + 2, 4);
            uint32_t ap[4];
            ap[0] = __float_as_uint(odd ? t1 : t0);
            ap[1] = __float_as_uint(odd ? t3 : t2);
            ap[2] = __float_as_uint(odd ? u1 : u0);
            ap[3] = __float_as_uint(odd ? u3 : u2);
            #pragma unroll
            for (int nt = 0; nt < 8; nt++) {
                uint2 bb = lds64(sm + SM_V + ((kt * 4 + q4) * VST + (nt * 8 + g) * 2) * 4);
                mma8(o[nt], ap, bb.x, bb.y);
            }
        }
    }

    // ---- Normalize and store ----
    float* ob = outg + (size_t)b * T * H;
    #pragma unroll
    for (int nt = 0; nt < 8; nt++) {
        float2 vlo = make_float2(o[nt][0] * inv_lo, o[nt][1] * inv_lo);
        float2 vhi = make_float2(o[nt][2] * inv_hi, o[nt][3] * inv_hi);
        *reinterpret_cast<float2*>(ob + r_lo * 64 + nt * 8 + 2 * q4) = vlo;
        *reinterpret_cast<float2*>(ob + r_hi * 64 + nt * 8 + 2 * q4) = vhi;
    }
}

// ------------------------------ launcher -----------------------------------

extern "C" void kernel_launch(void* const* d_in, const int* in_sizes, int n_in,
                              void* d_out, int out_size) {
    const float* x  = (const float*)d_in[0];
    const float* wq = (const float*)d_in[1];
    const float* wk = (const float*)d_in[2];
    const float* wv = (const float*)d_in[3];
    float* out = (float*)d_out;
    const int nb = in_sizes[0] / (T * C);

    cudaFuncSetAttribute(attn_head_kernel,
                         cudaFuncAttributeMaxDynamicSharedMemorySize, (int)SM_TOT);
    attn_head_kernel<<<nb, 256, SM_TOT>>>(x, wq, wk, wv, out);
}

// round 8
// speedup vs baseline: 1.0908x; 1.0908x over previous
#include <cuda_runtime.h>
#include <cstdint>

// ---------------------------------------------------------------------------
// Fused causal attention head via warp-level tf32 mma.sync. One CTA per batch,
// 2 CTAs/SM. Q and P in registers. SMEM uses an interleaved-group layout:
// each 8-wide k-group holds words [c0,c4,c1,c5,c2,c6,c3,c7]; X/W/K rows have
// 8 groups at staggered 16B-aligned bases {0,8,16,24,36,44,52,60} (stride 72
// words) so staging is pure STS.128 and every mma B-fragment pair (k,k+4) is
// one conflict-free LDS.64. V^T rows have 16 groups at PLAIN bases kt*8
// (stride 136 words; no STS.128 staging needed, and staggered bases would
// overflow the row -- that was the R7 OOB crash).
//   x:[4096,128,64] f32, Wq/Wk/Wv:[64,64] f32, out:[4096,128,64] f32
// ---------------------------------------------------------------------------

#define DEVINL __device__ __forceinline__

static constexpr int T = 128;
static constexpr int C = 64;
static constexpr int H = 64;

static constexpr int RST = 72;    // row stride (words) for W / X / K (72%32==8)
static constexpr int VST = 136;   // row stride (words) for V^T (136%32==8)

static constexpr uint32_t WSZ  = 64 * RST * 4;            // 18432 per W matrix
static constexpr uint32_t SM_W = 0;                       // Wk@0, Wv@18432; Wq later @0
static constexpr uint32_t SM_K = 2 * WSZ;                 // 36864 (X staged here first)
static constexpr uint32_t SM_X = SM_K;
static constexpr uint32_t SM_V = SM_K + 128 * RST * 4;    // 73728
static constexpr uint32_t SM_TOT = SM_V + 64 * VST * 4;   // 108544 -> 2 CTAs/SM

// staggered group base (words) of 8-wide k-group kt within an 8-group row
DEVINL constexpr int gb8(int kt)  { return kt * 8 + (kt >> 2) * 4; }

DEVINL uint32_t f2tf(float f) {
    uint32_t r; asm("cvt.rna.tf32.f32 %0, %1;" : "=r"(r) : "f"(f)); return r;
}
DEVINL float ex2f(float x) {
    float y; asm("ex2.approx.ftz.f32 %0, %1;" : "=f"(y) : "f"(x)); return y;
}
DEVINL void sts32(uint32_t a, uint32_t v) {
    asm volatile("st.shared.b32 [%0], %1;" :: "r"(a), "r"(v) : "memory");
}
DEVINL void sts128(uint32_t a, uint32_t r0, uint32_t r1, uint32_t r2, uint32_t r3) {
    asm volatile("st.shared.v4.b32 [%0], {%1,%2,%3,%4};"
                 :: "r"(a), "r"(r0), "r"(r1), "r"(r2), "r"(r3) : "memory");
}
DEVINL uint2 lds64(uint32_t a) {
    uint2 v;
    asm volatile("ld.shared.v2.b32 {%0,%1}, [%2];" : "=r"(v.x), "=r"(v.y) : "r"(a));
    return v;
}

// D += A(16x8) * B(8x8), tf32, fp32 accum
DEVINL void mma8(float d[4], const uint32_t a[4], uint32_t b0, uint32_t b1) {
    asm volatile(
        "mma.sync.aligned.m16n8k8.row.col.f32.tf32.tf32.f32 "
        "{%0,%1,%2,%3}, {%4,%5,%6,%7}, {%8,%9}, {%0,%1,%2,%3};"
        : "+f"(d[0]), "+f"(d[1]), "+f"(d[2]), "+f"(d[3])
        : "r"(a[0]), "r"(a[1]), "r"(a[2]), "r"(a[3]), "r"(b0), "r"(b1));
}

extern "C" __global__ void __launch_bounds__(256, 2)
attn_head_kernel(const float* __restrict__ xg, const float* __restrict__ wqg,
                 const float* __restrict__ wkg, const float* __restrict__ wvg,
                 float* __restrict__ outg)
{
    extern __shared__ __align__(16) char smc[];
    const uint32_t sm = [&] { uint32_t a;
        asm("{ .reg .u64 t; cvta.to.shared.u64 t, %1; cvt.u32.u64 %0, t; }"
            : "=r"(a) : "l"(smc)); return a; }();
    const int tid  = threadIdx.x;
    const int lane = tid & 31;
    const int w    = tid >> 5;          // warp 0..7
    const int b    = blockIdx.x;
    const int g    = lane >> 2;         // group id 0..7
    const int q4   = lane & 3;          // thread-in-group 0..3
    const int r_lo = 16 * w + g;        // CTA-local rows owned by this lane
    const int r_hi = r_lo + 8;
    const bool odd = (q4 & 1);
    const int half = q4 >> 1;
    const int posA = ((q4 & 1) << 2) | (q4 >> 1);   // pos of col 2*q4 in its group
    const int pg   = 2 * (g & 3) + (g >> 2);        // pos of token-in-group g
    const int g16lo = 16 * w;                       // PLAIN base of token group 2w

    // ---- Prefetch Wq group pairs into registers (staged to SMEM later) ----
    float4 wql[2], wqh[2];
    {
        const float4* wq4 = reinterpret_cast<const float4*>(wqg);
        #pragma unroll
        for (int j = 0; j < 2; j++) {
            int i = tid + j * 256;          // group id 0..511
            int row = i >> 3, grp = i & 7;
            wql[j] = wq4[row * 16 + grp * 2];
            wqh[j] = wq4[row * 16 + grp * 2 + 1];
        }
    }

    // ---- Stage X into SM_X (interleaved-group layout, pure STS.128) ----
    {
        const float4* xp4 = reinterpret_cast<const float4*>(xg + (size_t)b * T * C);
        #pragma unroll
        for (int j = 0; j < 4; j++) {
            int i = tid + j * 256;          // group id 0..1023
            int row = i >> 3, grp = i & 7;
            float4 lo = xp4[row * 16 + grp * 2];
            float4 hi = xp4[row * 16 + grp * 2 + 1];
            uint32_t base = sm + SM_X + (row * RST + gb8(grp)) * 4;
            sts128(base,      f2tf(lo.x), f2tf(hi.x), f2tf(lo.y), f2tf(hi.y));
            sts128(base + 16, f2tf(lo.z), f2tf(hi.z), f2tf(lo.w), f2tf(hi.w));
        }
    }
    // ---- Stage Wk, Wv ----
    #pragma unroll
    for (int m = 0; m < 2; m++) {
        const float4* wp4 = reinterpret_cast<const float4*>((m == 0) ? wkg : wvg);
        #pragma unroll
        for (int j = 0; j < 2; j++) {
            int i = tid + j * 256;          // group id 0..511
            int row = i >> 3, grp = i & 7;
            float4 lo = wp4[row * 16 + grp * 2];
            float4 hi = wp4[row * 16 + grp * 2 + 1];
            uint32_t base = sm + SM_W + m * WSZ + (row * RST + gb8(grp)) * 4;
            sts128(base,      f2tf(lo.x), f2tf(hi.x), f2tf(lo.y), f2tf(hi.y));
            sts128(base + 16, f2tf(lo.z), f2tf(hi.z), f2tf(lo.w), f2tf(hi.w));
        }
    }
    __syncthreads();

    // ---- A-fragments of X (LDS.64, conflict-free) ----
    uint32_t ax[8][4];
    #pragma unroll
    for (int kt = 0; kt < 8; kt++) {
        uint2 lo = lds64(sm + SM_X + (r_lo * RST + gb8(kt) + 2 * q4) * 4);
        uint2 hi = lds64(sm + SM_X + (r_hi * RST + gb8(kt) + 2 * q4) * 4);
        ax[kt][0] = lo.x; ax[kt][2] = lo.y;   // cols q4, q4+4 of row r_lo
        ax[kt][1] = hi.x; ax[kt][3] = hi.y;   // cols q4, q4+4 of row r_hi
    }
    __syncthreads();   // X region now dead; K may overwrite it

    // ---- Phase 1a: K = X*Wk^T -> SM_K (paired-k), V = X*Wv^T -> SM_V (V^T) ----
    #pragma unroll
    for (int m = 0; m < 2; m++) {
        const uint32_t wbase = sm + SM_W + m * WSZ;
        #pragma unroll
        for (int nt = 0; nt < 8; nt++) {
            float acc[4] = {0.f, 0.f, 0.f, 0.f};
            #pragma unroll
            for (int kt = 0; kt < 8; kt++) {
                uint2 bb = lds64(wbase + ((nt * 8 + g) * RST + gb8(kt) + 2 * q4) * 4);
                mma8(acc, ax[kt], bb.x, bb.y);
            }
            if (m == 0) {
                // K[token][feat] paired along feat: cols 2q4 -> posA, 2q4+1 -> posA+2
                uint32_t a0 = sm + SM_K + (r_lo * RST + gb8(nt) + posA) * 4;
                sts32(a0, f2tf(acc[0])); sts32(a0 + 8, f2tf(acc[1]));
                uint32_t a1 = sm + SM_K + (r_hi * RST + gb8(nt) + posA) * 4;
                sts32(a1, f2tf(acc[2])); sts32(a1 + 8, f2tf(acc[3]));
            } else {
                // V^T[feat][token], plain group bases: token r_lo in group 2w @ pos pg
                int nrow = nt * 8 + 2 * q4;
                uint32_t a0 = sm + SM_V + (nrow * VST + g16lo + pg) * 4;
                sts32(a0, f2tf(acc[0]));                   // (nrow  , r_lo)
                sts32(a0 + VST * 4, f2tf(acc[1]));         // (nrow+1, r_lo)
                uint32_t a2 = a0 + 8 * 4;                  // token group 2w+1 = +8 words
                sts32(a2, f2tf(acc[2]));                   // (nrow  , r_hi)
                sts32(a2 + VST * 4, f2tf(acc[3]));         // (nrow+1, r_hi)
            }
        }
    }
    __syncthreads();   // K/V complete; Wk region free

    // ---- Phase 1b: stage Wq (pre-scaled by 1/sqrt(64)) over Wk region ----
    #pragma unroll
    for (int j = 0; j < 2; j++) {
        int i = tid + j * 256;
        int row = i >> 3, grp = i & 7;
        float4 lo = wql[j], hi = wqh[j];
        uint32_t base = sm + SM_W + (row * RST + gb8(grp)) * 4;
        sts128(base,      f2tf(lo.x * 0.125f), f2tf(hi.x * 0.125f),
                          f2tf(lo.y * 0.125f), f2tf(hi.y * 0.125f));
        sts128(base + 16, f2tf(lo.z * 0.125f), f2tf(hi.z * 0.125f),
                          f2tf(lo.w * 0.125f), f2tf(hi.w * 0.125f));
    }
    __syncthreads();

    // ---- Phase 1c: Q = X*Wq^T -> registers (accumulator layout) ----
    float q[8][4];
    #pragma unroll
    for (int nt = 0; nt < 8; nt++) {
        q[nt][0] = q[nt][1] = q[nt][2] = q[nt][3] = 0.f;
        #pragma unroll
        for (int kt = 0; kt < 8; kt++) {
            uint2 bb = lds64(sm + SM_W + ((nt * 8 + g) * RST + gb8(kt) + 2 * q4) * 4);
            mma8(q[nt], ax[kt], bb.x, bb.y);
        }
    }

    // ---- Accum layout -> A-fragment layout via quad shuffles ----
    uint32_t aq[8][4];
    #pragma unroll
    for (int kt = 0; kt < 8; kt++) {
        float t0 = __shfl_sync(~0u, q[kt][0], half, 4);
        float t1 = __shfl_sync(~0u, q[kt][1], half, 4);
        float t2 = __shfl_sync(~0u, q[kt][2], half, 4);
        float t3 = __shfl_sync(~0u, q[kt][3], half, 4);
        float u0 = __shfl_sync(~0u, q[kt][0], half + 2, 4);
        float u1 = __shfl_sync(~0u, q[kt][1], half + 2, 4);
        float u2 = __shfl_sync(~0u, q[kt][2], half + 2, 4);
        float u3 = __shfl_sync(~0u, q[kt][3], half + 2, 4);
        aq[kt][0] = f2tf(odd ? t1 : t0);
        aq[kt][1] = f2tf(odd ? t3 : t2);
        aq[kt][2] = f2tf(odd ? u1 : u0);
        aq[kt][3] = f2tf(odd ? u3 : u2);
    }

    // ---- Phase 2: S = Q * K^T (causal: skip fully-masked n-tiles) ----
    float s[16][4];
    #pragma unroll
    for (int nt = 0; nt < 16; nt++)
        s[nt][0] = s[nt][1] = s[nt][2] = s[nt][3] = 0.f;
    const int tile_max = 2 * w + 2;
    #pragma unroll
    for (int nt = 0; nt < 16; nt++) {
        if (nt < tile_max) {
            #pragma unroll
            for (int kt = 0; kt < 8; kt++) {
                uint2 bb = lds64(sm + SM_K + ((nt * 8 + g) * RST + gb8(kt) + 2 * q4) * 4);
                mma8(s[nt], aq[kt], bb.x, bb.y);
            }
        }
    }

    // ---- Causal softmax in registers (row spread over a lane quad) ----
    float m_lo = -1e30f, m_hi = -1e30f;
    #pragma unroll
    for (int nt = 0; nt < 16; nt++) {
        #pragma unroll
        for (int e = 0; e < 2; e++) {
            int col = nt * 8 + 2 * q4 + e;
            if (col <= r_lo) m_lo = fmaxf(m_lo, s[nt][e]);
            if (col <= r_hi) m_hi = fmaxf(m_hi, s[nt][2 + e]);
        }
    }
    m_lo = fmaxf(m_lo, __shfl_xor_sync(~0u, m_lo, 1));
    m_lo = fmaxf(m_lo, __shfl_xor_sync(~0u, m_lo, 2));
    m_hi = fmaxf(m_hi, __shfl_xor_sync(~0u, m_hi, 1));
    m_hi = fmaxf(m_hi, __shfl_xor_sync(~0u, m_hi, 2));

    const float L2E = 1.4426950408889634f;
    float sum_lo = 0.f, sum_hi = 0.f;
    #pragma unroll
    for (int nt = 0; nt < 16; nt++) {
        #pragma unroll
        for (int e = 0; e < 2; e++) {
            int col = nt * 8 + 2 * q4 + e;
            float pl = (col <= r_lo) ? ex2f((s[nt][e]     - m_lo) * L2E) : 0.f;
            float ph = (col <= r_hi) ? ex2f((s[nt][2 + e] - m_hi) * L2E) : 0.f;
            sum_lo += pl; sum_hi += ph;
            s[nt][e]     = __uint_as_float(f2tf(pl));   // P, tf32 bits, accum layout
            s[nt][2 + e] = __uint_as_float(f2tf(ph));
        }
    }
    sum_lo += __shfl_xor_sync(~0u, sum_lo, 1);
    sum_lo += __shfl_xor_sync(~0u, sum_lo, 2);
    sum_hi += __shfl_xor_sync(~0u, sum_hi, 1);
    sum_hi += __shfl_xor_sync(~0u, sum_hi, 2);
    const float inv_lo = 1.f / sum_lo, inv_hi = 1.f / sum_hi;

    // ---- Phase 4: O = P * V (P -> A-frags on the fly; V^T via LDS.64) ----
    float o[8][4];
    #pragma unroll
    for (int nt = 0; nt < 8; nt++)
        o[nt][0] = o[nt][1] = o[nt][2] = o[nt][3] = 0.f;
    #pragma unroll
    for (int kt = 0; kt < 16; kt++) {
        if (kt < tile_max) {
            float t0 = __shfl_sync(~0u, s[kt][0], half, 4);
            float t1 = __shfl_sync(~0u, s[kt][1], half, 4);
            float t2 = __shfl_sync(~0u, s[kt][2], half, 4);
            float t3 = __shfl_sync(~0u, s[kt][3], half, 4);
            float u0 = __shfl_sync(~0u, s[kt][0], half + 2, 4);
            float u1 = __shfl_sync(~0u, s[kt][1], half + 2, 4);
            float u2 = __shfl_sync(~0u, s[kt][2], half + 2, 4);
            float u3 = __shfl_sync(~0u, s[kt][3], half + 2, 4);
            uint32_t ap[4];
            ap[0] = __float_as_uint(odd ? t1 : t0);
            ap[1] = __float_as_uint(odd ? t3 : t2);
            ap[2] = __float_as_uint(odd ? u1 : u0);
            ap[3] = __float_as_uint(odd ? u3 : u2);
            #pragma unroll
            for (int nt = 0; nt < 8; nt++) {
                uint2 bb = lds64(sm + SM_V + ((nt * 8 + g) * VST + kt * 8 + 2 * q4) * 4);
                mma8(o[nt], ap, bb.x, bb.y);
            }
        }
    }

    // ---- Normalize and store ----
    float* ob = outg + (size_t)b * T * H;
    #pragma unroll
    for (int nt = 0; nt < 8; nt++) {
        float2 vlo = make_float2(o[nt][0] * inv_lo, o[nt][1] * inv_lo);
        float2 vhi = make_float2(o[nt][2] * inv_hi, o[nt][3] * inv_hi);
        *reinterpret_cast<float2*>(ob + r_lo * 64 + nt * 8 + 2 * q4) = vlo;
        *reinterpret_cast<float2*>(ob + r_hi * 64 + nt * 8 + 2 * q4) = vhi;
    }
}

// ------------------------------ launcher -----------------------------------

extern "C" void kernel_launch(void* const* d_in, const int* in_sizes, int n_in,
                              void* d_out, int out_size) {
    const float* x  = (const float*)d_in[0];
    const float* wq = (const float*)d_in[1];
    const float* wk = (const float*)d_in[2];
    const float* wv = (const float*)d_in[3];
    float* out = (float*)d_out;
    const int nb = in_sizes[0] / (T * C);

    cudaFuncSetAttribute(attn_head_kernel,
                         cudaFuncAttributeMaxDynamicSharedMemorySize, (int)SM_TOT);
    attn_head_kernel<<<nb, 256, SM_TOT>>>(x, wq, wk, wv, out);
}

// round 10
// speedup vs baseline: 1.1279x; 1.0341x over previous
#include <cuda_runtime.h>
#include <cstdint>

// ---------------------------------------------------------------------------
// Fused causal attention head via warp-level tf32 mma.sync. One CTA per batch,
// 2 CTAs/SM. KEY IDEA: use a permuted k-mapping inside every mma -- lane q4
// supplies k = (2q4, 2q4+1) instead of (q4, q4+4) on BOTH A and B (dot product
// unchanged). Consequences: accumulator layout == A-fragment layout (Q and P
// convert by register renaming, zero shuffles), all SMEM layouts are plain
// row-major (pairs adjacent), X loads directly from gmem as sector-perfect
// LDG.64. Q and P never touch SMEM.
//   x:[4096,128,64] f32, Wq/Wk/Wv:[64,64] f32, out:[4096,128,64] f32
// ---------------------------------------------------------------------------

#define DEVINL __device__ __forceinline__

static constexpr int T = 128;
static constexpr int C = 64;
static constexpr int H = 64;

static constexpr int RST = 72;    // row stride (words) W / K   (72  % 32 == 8)
static constexpr int VST = 136;   // row stride (words) V^T     (136 % 32 == 8)

static constexpr uint32_t WSZ  = 64 * RST * 4;            // 18432 per W matrix
static constexpr uint32_t SM_W = 0;                       // Wk@0, Wv@18432
static constexpr uint32_t SM_K = 2 * WSZ;                 // 36864: Wq staged here, then K
static constexpr uint32_t SM_V = SM_K + 128 * RST * 4;    // 73728: V^T 64x136
static constexpr uint32_t SM_TOT = SM_V + 64 * VST * 4;   // 108544 -> 2 CTAs/SM

DEVINL uint32_t f2tf(float f) {
    uint32_t r; asm("cvt.rna.tf32.f32 %0, %1;" : "=r"(r) : "f"(f)); return r;
}
DEVINL float ex2f(float x) {
    float y; asm("ex2.approx.ftz.f32 %0, %1;" : "=f"(y) : "f"(x)); return y;
}
DEVINL void sts32(uint32_t a, uint32_t v) {
    asm volatile("st.shared.b32 [%0], %1;" :: "r"(a), "r"(v) : "memory");
}
DEVINL void sts64(uint32_t a, uint32_t v0, uint32_t v1) {
    asm volatile("st.shared.v2.b32 [%0], {%1,%2};" :: "r"(a), "r"(v0), "r"(v1) : "memory");
}
DEVINL void sts128(uint32_t a, uint32_t r0, uint32_t r1, uint32_t r2, uint32_t r3) {
    asm volatile("st.shared.v4.b32 [%0], {%1,%2,%3,%4};"
                 :: "r"(a), "r"(r0), "r"(r1), "r"(r2), "r"(r3) : "memory");
}
DEVINL uint2 lds64(uint32_t a) {
    uint2 v;
    asm volatile("ld.shared.v2.b32 {%0,%1}, [%2];" : "=r"(v.x), "=r"(v.y) : "r"(a));
    return v;
}

// D += A(16x8) * B(8x8), tf32, fp32 accum.
// Permuted-k convention: frag slot q4 carries k=2q4, slot q4+4 carries k=2q4+1.
DEVINL void mma8(float d[4], const uint32_t a[4], uint32_t b0, uint32_t b1) {
    asm volatile(
        "mma.sync.aligned.m16n8k8.row.col.f32.tf32.tf32.f32 "
        "{%0,%1,%2,%3}, {%4,%5,%6,%7}, {%8,%9}, {%0,%1,%2,%3};"
        : "+f"(d[0]), "+f"(d[1]), "+f"(d[2]), "+f"(d[3])
        : "r"(a[0]), "r"(a[1]), "r"(a[2]), "r"(a[3]), "r"(b0), "r"(b1));
}

extern "C" __global__ void __launch_bounds__(256, 2)
attn_head_kernel(const float* __restrict__ xg, const float* __restrict__ wqg,
                 const float* __restrict__ wkg, const float* __restrict__ wvg,
                 float* __restrict__ outg)
{
    extern __shared__ __align__(16) char smc[];
    const uint32_t sm = [&] { uint32_t a;
        asm("{ .reg .u64 t; cvta.to.shared.u64 t, %1; cvt.u32.u64 %0, t; }"
            : "=r"(a) : "l"(smc)); return a; }();
    const int tid  = threadIdx.x;
    const int lane = tid & 31;
    const int w    = tid >> 5;          // warp 0..7
    const int b    = blockIdx.x;
    const int g    = lane >> 2;         // group id 0..7
    const int q4   = lane & 3;          // thread-in-group 0..3
    const int r_lo = 16 * w + g;        // CTA-local rows owned by this lane
    const int r_hi = r_lo + 8;

    // ---- X A-fragments straight from gmem: LDG.64 float2 (sector-perfect) ----
    const float2* xb2 = reinterpret_cast<const float2*>(xg + (size_t)b * T * C);
    float2 xlo[8], xhi[8];
    #pragma unroll
    for (int kt = 0; kt < 8; kt++) {
        xlo[kt] = xb2[r_lo * 32 + kt * 4 + q4];
        xhi[kt] = xb2[r_hi * 32 + kt * 4 + q4];
    }

    // ---- Stage Wk@0, Wv@18432, Wq(pre-scaled)@SM_K. Plain row-major. ----
    #pragma unroll
    for (int m = 0; m < 3; m++) {
        const float4* wp4 = reinterpret_cast<const float4*>(
            (m == 0) ? wkg : ((m == 1) ? wvg : wqg));
        const uint32_t base = sm + ((m == 2) ? SM_K : m * WSZ);
        const float sc = (m == 2) ? 0.125f : 1.0f;   // fold 1/sqrt(64) into Wq
        #pragma unroll
        for (int j = 0; j < 4; j++) {
            int i = tid + j * 256;          // 0..1023 float4
            int row = i >> 4, c4 = i & 15;
            float4 v = wp4[i];
            sts128(base + (row * RST + c4 * 4) * 4,
                   f2tf(v.x * sc), f2tf(v.y * sc), f2tf(v.z * sc), f2tf(v.w * sc));
        }
    }

    // ---- Build X frags (permuted-k: slots = cols 2q4, 2q4+1) ----
    uint32_t ax[8][4];
    #pragma unroll
    for (int kt = 0; kt < 8; kt++) {
        ax[kt][0] = f2tf(xlo[kt].x);   // (r_lo, 2q4)
        ax[kt][1] = f2tf(xhi[kt].x);   // (r_hi, 2q4)
        ax[kt][2] = f2tf(xlo[kt].y);   // (r_lo, 2q4+1)
        ax[kt][3] = f2tf(xhi[kt].y);   // (r_hi, 2q4+1)
    }
    __syncthreads();

    // ---- Q = X*Wq^T -> registers (accumulator layout; Wq lives in SM_K) ----
    float q[8][4];
    #pragma unroll
    for (int nt = 0; nt < 8; nt++) {
        q[nt][0] = q[nt][1] = q[nt][2] = q[nt][3] = 0.f;
        #pragma unroll
        for (int kt = 0; kt < 8; kt++) {
            uint2 bb = lds64(sm + SM_K + ((nt * 8 + g) * RST + kt * 8 + 2 * q4) * 4);
            mma8(q[nt], ax[kt], bb.x, bb.y);
        }
    }
    __syncthreads();   // all warps done reading Wq before K overwrites SM_K

    // ---- K = X*Wk^T -> SM_K (row-major), V = X*Wv^T -> SM_V (V^T row-major) ----
    #pragma unroll
    for (int m = 0; m < 2; m++) {
        const uint32_t wbase = sm + m * WSZ;
        #pragma unroll
        for (int nt = 0; nt < 8; nt++) {
            float acc[4] = {0.f, 0.f, 0.f, 0.f};
            #pragma unroll
            for (int kt = 0; kt < 8; kt++) {
                uint2 bb = lds64(wbase + ((nt * 8 + g) * RST + kt * 8 + 2 * q4) * 4);
                mma8(acc, ax[kt], bb.x, bb.y);
            }
            if (m == 0) {
                // K[token][feat]: accum cols are adjacent -> STS.64
                sts64(sm + SM_K + (r_lo * RST + nt * 8 + 2 * q4) * 4,
                      f2tf(acc[0]), f2tf(acc[1]));
                sts64(sm + SM_K + (r_hi * RST + nt * 8 + 2 * q4) * 4,
                      f2tf(acc[2]), f2tf(acc[3]));
            } else {
                // V^T[feat][token]: feat = nt*8+2q4 (+1), token = r_lo / r_hi
                uint32_t f0 = sm + SM_V + ((nt * 8 + 2 * q4) * VST) * 4;
                sts32(f0 + r_lo * 4,           f2tf(acc[0]));
                sts32(f0 + (VST + r_lo) * 4,   f2tf(acc[1]));
                sts32(f0 + r_hi * 4,           f2tf(acc[2]));
                sts32(f0 + (VST + r_hi) * 4,   f2tf(acc[3]));
            }
        }
    }
    __syncthreads();   // K/V visible to all warps

    // ---- A-frags of Q: pure register rename (accum layout == frag layout) ----
    uint32_t aq[8][4];
    #pragma unroll
    for (int kt = 0; kt < 8; kt++) {
        aq[kt][0] = f2tf(q[kt][0]);   // (r_lo, 2q4)
        aq[kt][1] = f2tf(q[kt][2]);   // (r_hi, 2q4)
        aq[kt][2] = f2tf(q[kt][1]);   // (r_lo, 2q4+1)
        aq[kt][3] = f2tf(q[kt][3]);   // (r_hi, 2q4+1)
    }

    // ---- Phase 2: S = Q * K^T (causal: skip fully-masked n-tiles) ----
    float s[16][4];
    #pragma unroll
    for (int nt = 0; nt < 16; nt++)
        s[nt][0] = s[nt][1] = s[nt][2] = s[nt][3] = 0.f;
    const int tile_max = 2 * w + 2;
    #pragma unroll
    for (int nt = 0; nt < 16; nt++) {
        if (nt < tile_max) {
            #pragma unroll
            for (int kt = 0; kt < 8; kt++) {
                uint2 bb = lds64(sm + SM_K + ((nt * 8 + g) * RST + kt * 8 + 2 * q4) * 4);
                mma8(s[nt], aq[kt], bb.x, bb.y);
            }
        }
    }

    // ---- Causal softmax in registers (row spread over a lane quad) ----
    float m_lo = -1e30f, m_hi = -1e30f;
    #pragma unroll
    for (int nt = 0; nt < 16; nt++) {
        #pragma unroll
        for (int e = 0; e < 2; e++) {
            int col = nt * 8 + 2 * q4 + e;
            if (col <= r_lo) m_lo = fmaxf(m_lo, s[nt][e]);
            if (col <= r_hi) m_hi = fmaxf(m_hi, s[nt][2 + e]);
        }
    }
    m_lo = fmaxf(m_lo, __shfl_xor_sync(~0u, m_lo, 1));
    m_lo = fmaxf(m_lo, __shfl_xor_sync(~0u, m_lo, 2));
    m_hi = fmaxf(m_hi, __shfl_xor_sync(~0u, m_hi, 1));
    m_hi = fmaxf(m_hi, __shfl_xor_sync(~0u, m_hi, 2));

    const float L2E = 1.4426950408889634f;
    float sum_lo = 0.f, sum_hi = 0.f;
    #pragma unroll
    for (int nt = 0; nt < 16; nt++) {
        #pragma unroll
        for (int e = 0; e < 2; e++) {
            int col = nt * 8 + 2 * q4 + e;
            float pl = (col <= r_lo) ? ex2f((s[nt][e]     - m_lo) * L2E) : 0.f;
            float ph = (col <= r_hi) ? ex2f((s[nt][2 + e] - m_hi) * L2E) : 0.f;
            sum_lo += pl; sum_hi += ph;
            s[nt][e]     = __uint_as_float(f2tf(pl));   // P, tf32 bits, accum layout
            s[nt][2 + e] = __uint_as_float(f2tf(ph));
        }
    }
    sum_lo += __shfl_xor_sync(~0u, sum_lo, 1);
    sum_lo += __shfl_xor_sync(~0u, sum_lo, 2);
    sum_hi += __shfl_xor_sync(~0u, sum_hi, 1);
    sum_hi += __shfl_xor_sync(~0u, sum_hi, 2);
    const float inv_lo = 1.f / sum_lo, inv_hi = 1.f / sum_hi;

    // ---- Phase 4: O = P * V. P A-frags = register rename of s[] ----
    float o[8][4];
    #pragma unroll
    for (int nt = 0; nt < 8; nt++)
        o[nt][0] = o[nt][1] = o[nt][2] = o[nt][3] = 0.f;
    #pragma unroll
    for (int kt = 0; kt < 16; kt++) {
        if (kt < tile_max) {
            uint32_t ap[4];
            ap[0] = __float_as_uint(s[kt][0]);   // (r_lo, token 2q4)
            ap[1] = __float_as_uint(s[kt][2]);   // (r_hi, token 2q4)
            ap[2] = __float_as_uint(s[kt][1]);   // (r_lo, token 2q4+1)
            ap[3] = __float_as_uint(s[kt][3]);   // (r_hi, token 2q4+1)
            #pragma unroll
            for (int nt = 0; nt < 8; nt++) {
                uint2 bb = lds64(sm + SM_V + ((nt * 8 + g) * VST + kt * 8 + 2 * q4) * 4);
                mma8(o[nt], ap, bb.x, bb.y);
            }
        }
    }

    // ---- Normalize and store ----
    float* ob = outg + (size_t)b * T * H;
    #pragma unroll
    for (int nt = 0; nt < 8; nt++) {
        float2 vlo = make_float2(o[nt][0] * inv_lo, o[nt][1] * inv_lo);
        float2 vhi = make_float2(o[nt][2] * inv_hi, o[nt][3] * inv_hi);
        *reinterpret_cast<float2*>(ob + r_lo * 64 + nt * 8 + 2 * q4) = vlo;
        *reinterpret_cast<float2*>(ob + r_hi * 64 + nt * 8 + 2 * q4) = vhi;
    }
}

// ------------------------------ launcher -----------------------------------

extern "C" void kernel_launch(void* const* d_in, const int* in_sizes, int n_in,
                              void* d_out, int out_size) {
    const float* x  = (const float*)d_in[0];
    const float* wq = (const float*)d_in[1];
    const float* wk = (const float*)d_in[2];
    const float* wv = (const float*)d_in[3];
    float* out = (float*)d_out;
    const int nb = in_sizes[0] / (T * C);

    cudaFuncSetAttribute(attn_head_kernel,
                         cudaFuncAttributeMaxDynamicSharedMemorySize, (int)SM_TOT);
    attn_head_kernel<<<nb, 256, SM_TOT>>>(x, wq, wk, wv, out);
}